// round 7
// baseline (speedup 1.0000x reference)
#include <cuda_runtime.h>
#include <math_constants.h>

#define VOCAB   512
#define MAXLEN  512
#define BATCH   128
#define NFEAT   (VOCAB + VOCAB * VOCAB + 2)   // 262658
#define NTHREADS 128                           // 4 positions per thread

__global__ __launch_bounds__(NTHREADS)
void ngram_logreg_kernel(const float4* __restrict__ x4,    // [B, 256] float4 = [B,512,2] f32
                         const int*    __restrict__ lengths,
                         const float*  __restrict__ W,     // [NFEAT]
                         const float*  __restrict__ bias,  // [1]
                         float*        __restrict__ out)   // [B]
{
    __shared__ float s_sum[NTHREADS / 32];   // 4 partials
    __shared__ float s_max[NTHREADS / 32];

    const int b = blockIdx.x;
    const int t = threadIdx.x;

    // ---- front-batch all independent loads ----
    const int len = __ldg(&lengths[b]);
    const float wt = __ldg(&W[NFEAT - 2]);
    const float wl = __ldg(&W[NFEAT - 1]);
    const float bb = __ldg(bias);

    const float4* row = x4 + (size_t)b * (MAXLEN / 2);
    float4 v0 = __ldg(&row[2 * t]);          // pos 4t   (x,y), 4t+1 (z,w)
    float4 v1 = __ldg(&row[2 * t + 1]);      // pos 4t+2 (x,y), 4t+3 (z,w)
    // action at pos 4t+4 (thread t+1's first); clamped index, value masked at t=127
    float a4f = __ldg((const float*)&row[(t < NTHREADS - 1) ? (2 * t + 2) : (2 * t)]);

    const int a0 = (int)v0.x;
    const int a1 = (int)v0.z;
    const int a2 = (int)v1.x;
    const int a3 = (int)v1.z;
    const int a4 = (int)a4f;

    const int base = 4 * t;
    const bool m0 = base + 0 < len;
    const bool m1 = base + 1 < len;
    const bool m2 = base + 2 < len;
    const bool m3 = base + 3 < len;
    const bool m4 = base + 4 < len;          // always false at t=127 (pos 512)

    // ---- predicated gathers: 4 unigrams + 4 bigrams, all independent ----
    float sum = 0.0f;
    if (m0) sum += __ldg(&W[a0]);
    if (m1) sum += __ldg(&W[a1]) + __ldg(&W[VOCAB + a0 * VOCAB + a1]);
    if (m2) sum += __ldg(&W[a2]) + __ldg(&W[VOCAB + a1 * VOCAB + a2]);
    if (m3) sum += __ldg(&W[a3]) + __ldg(&W[VOCAB + a2 * VOCAB + a3]);
    if (m4) sum += __ldg(&W[VOCAB + a3 * VOCAB + a4]);

    float tmax = -CUDART_INF_F;
    if (m0) tmax = v0.y;
    if (m1) tmax = fmaxf(tmax, v0.w);
    if (m2) tmax = fmaxf(tmax, v1.y);
    if (m3) tmax = fmaxf(tmax, v1.w);

    // ---- warp reduce ----
    #pragma unroll
    for (int off = 16; off > 0; off >>= 1) {
        sum  += __shfl_xor_sync(0xFFFFFFFFu, sum,  off);
        tmax  = fmaxf(tmax, __shfl_xor_sync(0xFFFFFFFFu, tmax, off));
    }
    const int wid = t >> 5;
    const int lid = t & 31;
    if (lid == 0) { s_sum[wid] = sum; s_max[wid] = tmax; }
    __syncthreads();

    // ---- final reduce over 4 partials in warp 0 ----
    if (t < 32) {
        sum  = (lid < NTHREADS / 32) ? s_sum[lid] : 0.0f;
        tmax = (lid < NTHREADS / 32) ? s_max[lid] : -CUDART_INF_F;
        #pragma unroll
        for (int off = 2; off > 0; off >>= 1) {
            sum  += __shfl_xor_sync(0xFFFFFFFFu, sum,  off);
            tmax  = fmaxf(tmax, __shfl_xor_sync(0xFFFFFFFFu, tmax, off));
        }
        if (lid == 0) {
            float total_time = (len > 0) ? tmax : 0.0f;   // len >= 1 per spec
            out[b] = sum + wt * total_time + wl * (float)len + bb;
        }
    }
}

extern "C" void kernel_launch(void* const* d_in, const int* in_sizes, int n_in,
                              void* d_out, int out_size)
{
    const float4* x       = (const float4*)d_in[0];  // [B, MAXLEN, 2] f32, 16B-aligned
    const int*    lengths = (const int*)   d_in[1];  // [B] int32
    const float*  W       = (const float*) d_in[2];  // [1, NFEAT] f32
    const float*  bias    = (const float*) d_in[3];  // [1] f32
    float*        out     = (float*)d_out;           // [B, 1] f32

    ngram_logreg_kernel<<<BATCH, NTHREADS>>>(x, lengths, W, bias, out);
}

// round 13
// speedup vs baseline: 1.0337x; 1.0337x over previous
#include <cuda_runtime.h>

#define VOCAB   512
#define MAXLEN  512
#define BATCH   128
#define NFEAT   (VOCAB + VOCAB * VOCAB + 2)   // 262658
#define NTHREADS 512                           // 1 position per thread
#define NWARPS  (NTHREADS / 32)                // 16

__global__ __launch_bounds__(NTHREADS)
void ngram_logreg_kernel(const float2* __restrict__ x2,    // [B, 512] of (action, time)
                         const int*    __restrict__ lengths,
                         const float*  __restrict__ W,     // [NFEAT]
                         const float*  __restrict__ bias,  // [1]
                         float*        __restrict__ out)   // [B]
{
    __shared__ float s_sum[NWARPS];
    __shared__ float s_max[NWARPS];

    const int b = blockIdx.x;
    const int t = threadIdx.x;                 // position index 0..511

    // ---- front-batch all independent loads ----
    const int len = __ldg(&lengths[b]);
    const float wt = __ldg(&W[NFEAT - 2]);
    const float wl = __ldg(&W[NFEAT - 1]);
    const float bb = __ldg(bias);

    const float2* row = x2 + (size_t)b * MAXLEN;
    float2 v = __ldg(&row[t]);                 // (action_t, time_t), coalesced 8B
    // action at position t+1 (clamped index; value only used when t+1 < len <= 512)
    float anf = __ldg((const float*)&row[(t < MAXLEN - 1) ? (t + 1) : t]);

    const int a0 = (int)v.x;
    const int a1 = (int)anf;

    const bool m0 = t < len;
    const bool m1 = t + 1 < len;               // always false at t=511

    // ---- at most 2 predicated gathers per thread ----
    float sum = 0.0f;
    if (m0) sum += __ldg(&W[a0]);                          // unigram
    if (m1) sum += __ldg(&W[VOCAB + a0 * VOCAB + a1]);     // bigram (t, t+1)

    float tmax = 0.0f;                         // times >= 0 and len >= 1
    if (m0) tmax = v.y;

    // ---- warp reduce ----
    #pragma unroll
    for (int off = 16; off > 0; off >>= 1) {
        sum  += __shfl_xor_sync(0xFFFFFFFFu, sum,  off);
        tmax  = fmaxf(tmax, __shfl_xor_sync(0xFFFFFFFFu, tmax, off));
    }
    const int wid = t >> 5;
    const int lid = t & 31;
    if (lid == 0) { s_sum[wid] = sum; s_max[wid] = tmax; }
    __syncthreads();

    // ---- final reduce over 16 partials in warp 0 ----
    if (t < 32) {
        sum  = (lid < NWARPS) ? s_sum[lid] : 0.0f;
        tmax = (lid < NWARPS) ? s_max[lid] : 0.0f;
        #pragma unroll
        for (int off = 8; off > 0; off >>= 1) {
            sum  += __shfl_xor_sync(0xFFFFFFFFu, sum,  off);
            tmax  = fmaxf(tmax, __shfl_xor_sync(0xFFFFFFFFu, tmax, off));
        }
        if (lid == 0) {
            out[b] = sum + wt * tmax + wl * (float)len + bb;
        }
    }
}

extern "C" void kernel_launch(void* const* d_in, const int* in_sizes, int n_in,
                              void* d_out, int out_size)
{
    const float2* x       = (const float2*)d_in[0];  // [B, MAXLEN, 2] f32
    const int*    lengths = (const int*)   d_in[1];  // [B] int32
    const float*  W       = (const float*) d_in[2];  // [1, NFEAT] f32
    const float*  bias    = (const float*) d_in[3];  // [1] f32
    float*        out     = (float*)d_out;           // [B, 1] f32

    ngram_logreg_kernel<<<BATCH, NTHREADS>>>(x, lengths, W, bias, out);
}

// round 17
// speedup vs baseline: 1.0386x; 1.0048x over previous
#include <cuda_runtime.h>

#define VOCAB   512
#define MAXLEN  512
#define BATCH   128
#define NFEAT   (VOCAB + VOCAB * VOCAB + 2)   // 262658
#define NTHREADS 256                           // 2 positions per thread (measured knee)
#define NWARPS  (NTHREADS / 32)                // 8

__global__ __launch_bounds__(NTHREADS)
void ngram_logreg_kernel(const float4* __restrict__ x4,    // [B, 256] float4 = [B,512,2] f32
                         const int*    __restrict__ lengths,
                         const float*  __restrict__ W,     // [NFEAT]
                         const float*  __restrict__ bias,  // [1]
                         float*        __restrict__ out)   // [B]
{
    __shared__ float s_sum[NWARPS];
    __shared__ float s_max[NWARPS];

    const int b   = blockIdx.x;
    const int t   = threadIdx.x;
    const int lid = t & 31;

    // ---- front-batch all independent loads ----
    const int len = __ldg(&lengths[b]);
    const float wt = __ldg(&W[NFEAT - 2]);
    const float wl = __ldg(&W[NFEAT - 1]);
    const float bb = __ldg(bias);

    const float4* row = x4 + (size_t)b * (MAXLEN / 2);
    float4 v = __ldg(&row[t]);                  // pos 2t (x,y), 2t+1 (z,w)

    // Only lane 31 needs a cross-warp lookahead load (action at pos 2t+2).
    float a2f = 0.0f;
    if (lid == 31 && t < NTHREADS - 1)
        a2f = __ldg((const float*)&row[t + 1]);

    const int a0 = (int)v.x;
    const int a1 = (int)v.z;
    // lanes 0..30: neighbor's a0 via shuffle; lane 31: the loaded value
    const int a2s = __shfl_down_sync(0xFFFFFFFFu, a0, 1);
    const int a2  = (lid == 31) ? (int)a2f : a2s;

    const int p0 = 2 * t, p1 = 2 * t + 1, p2 = 2 * t + 2;
    const bool m0 = p0 < len;
    const bool m1 = p1 < len;
    const bool m2 = p2 < len;                   // always false at t=255 (p2=512)

    // ---- predicated gathers ----
    float sum = 0.0f;
    if (m0) sum += __ldg(&W[a0]);                          // unigram(2t)
    if (m1) sum += __ldg(&W[a1])                           // unigram(2t+1)
                 + __ldg(&W[VOCAB + a0 * VOCAB + a1]);     // bigram(2t,2t+1)
    if (m2) sum += __ldg(&W[VOCAB + a1 * VOCAB + a2]);     // bigram(2t+1,2t+2)

    float tmax = 0.0f;                          // times >= 0, len >= 1
    if (m0) tmax = v.y;
    if (m1) tmax = fmaxf(tmax, v.w);

    // ---- warp reduce ----
    #pragma unroll
    for (int off = 16; off > 0; off >>= 1) {
        sum  += __shfl_xor_sync(0xFFFFFFFFu, sum,  off);
        tmax  = fmaxf(tmax, __shfl_xor_sync(0xFFFFFFFFu, tmax, off));
    }
    const int wid = t >> 5;
    if (lid == 0) { s_sum[wid] = sum; s_max[wid] = tmax; }
    __syncthreads();

    // ---- final reduce over 8 partials in warp 0 ----
    if (t < 32) {
        sum  = (lid < NWARPS) ? s_sum[lid] : 0.0f;
        tmax = (lid < NWARPS) ? s_max[lid] : 0.0f;
        #pragma unroll
        for (int off = 4; off > 0; off >>= 1) {
            sum  += __shfl_xor_sync(0xFFFFFFFFu, sum,  off);
            tmax  = fmaxf(tmax, __shfl_xor_sync(0xFFFFFFFFu, tmax, off));
        }
        if (lid == 0) {
            out[b] = sum + wt * tmax + wl * (float)len + bb;
        }
    }
}

extern "C" void kernel_launch(void* const* d_in, const int* in_sizes, int n_in,
                              void* d_out, int out_size)
{
    const float4* x       = (const float4*)d_in[0];  // [B, MAXLEN, 2] f32, 16B-aligned
    const int*    lengths = (const int*)   d_in[1];  // [B] int32
    const float*  W       = (const float*) d_in[2];  // [1, NFEAT] f32
    const float*  bias    = (const float*) d_in[3];  // [1] f32
    float*        out     = (float*)d_out;           // [B, 1] f32

    ngram_logreg_kernel<<<BATCH, NTHREADS>>>(x, lengths, W, bias, out);
}